// round 5
// baseline (speedup 1.0000x reference)
#include <cuda_runtime.h>

// BEVFeatureExtractorV2 — R5: single fused launch = sequential L2 prefetch + gather.
// feats: (B=4, C=256, H=256, W=256) fp32   rois: (B=4, N=512, 7) fp32
// out: (B, N, 5*C) fp32
//
// R4 showed L2 already dedups all reuse (per-batch working set < L2), so traffic
// is compulsory (~250MB). Bottleneck = DRAM efficiency on temporally-random 128B
// lines (5.3 of 8 TB/s). Fix: dedicated prefetch blocks stream the touched row
// band (y in [6,251], contiguous 246KB per plane) sequentially into L2 via
// prefetch.global.L2; gather blocks then mostly L2-hit, and the DRAM request
// stream is mostly sequential.

#define BB 4
#define NN 512
#define CC 256
#define HH 256
#define WW 256
#define NPTS 5
#define HWSZ (HH * WW)

#define ROW_LO 6
#define ROW_HI 252                       // exclusive; taps live in y in [6,251]
#define PF_BYTES ((ROW_HI - ROW_LO) * WW * 4)   // 246 * 1024 = 251904 B / plane
#define PF_LINES (PF_BYTES / 128)               // 1968 lines per plane

#define THREADS 128
#define NPF_BLK CC                        // 256 prefetch blocks per batch (1 plane each)
#define PTS_PER_BATCH (NN * NPTS)         // 2560
#define NG_BLK (PTS_PER_BATCH / 4)        // 640 gather blocks per batch (4 warps)
#define SEG (NPF_BLK + NG_BLK)            // 896 blocks per batch

__device__ __forceinline__ float f4_get(const float4& v, int i) {
    return (i == 0) ? v.x : (i == 1) ? v.y : (i == 2) ? v.z : v.w;
}

__global__ __launch_bounds__(THREADS) void bev_fused_kernel(
    const float* __restrict__ feats,
    const float* __restrict__ rois,
    float* __restrict__ out)
{
    const int seg   = blockIdx.x;
    const int batch = seg / SEG;
    const int r     = seg % SEG;

    if (r < NPF_BLK) {
        // ---- Prefetch block: stream plane (batch, c=r), rows [ROW_LO, ROW_HI) ----
        const int c = r;
        const char* base = (const char*)(feats + ((size_t)batch * CC + c) * HWSZ
                                               + ROW_LO * WW);
        const int t = threadIdx.x;
        #pragma unroll
        for (int l = 0; l < (PF_LINES + THREADS - 1) / THREADS; l++) {
            const int idx = t + THREADS * l;
            if (idx < PF_LINES) {
                asm volatile("prefetch.global.L2 [%0];" :: "l"(base + (size_t)idx * 128));
            }
        }
        return;
    }

    // ---- Gather block: 4 warps, one (roi, point) each ----
    const int warp = threadIdx.x >> 5;
    const int lane = threadIdx.x & 31;
    const int local = (r - NPF_BLK) * 4 + warp;        // point within batch, 0..2559
    const int p = local % NPTS;
    const int n = local / NPTS;
    const int b = batch;

    const float* roi = rois + (b * NN + n) * 7;
    const float cx = roi[0];
    const float cy = roi[1];
    const float dx = roi[3];
    const float dy = roi[4];
    const float ry = roi[6];

    float sn, cs;
    sincosf(ry, &sn, &cs);

    // rot(x, y) = (x*cos + y*sin, -x*sin + y*cos)  (row-vector * R)
    float px = cx, py = cy;
    const float hx = 0.5f * dx, hy = 0.5f * dy;
    if (p == 1)      { px = cx - hx * cs; py = cy + hx * sn; }
    else if (p == 2) { px = cx + hx * cs; py = cy - hx * sn; }
    else if (p == 3) { px = cx - hy * sn; py = cy - hy * cs; }
    else if (p == 4) { px = cx + hy * sn; py = cy + hy * cs; }

    const float x = (px + 51.2f) / 0.1f / 4.0f;
    const float y = (py + 51.2f) / 0.1f / 4.0f;

    const float xf = floorf(x);
    const float yf = floorf(y);
    int x0 = (int)xf,  x1 = (int)xf + 1;
    int y0 = (int)yf,  y1 = (int)yf + 1;
    x0 = min(max(x0, 0), WW - 1);
    x1 = min(max(x1, 0), WW - 1);
    y0 = min(max(y0, 0), HH - 1);
    y1 = min(max(y1, 0), HH - 1);

    const float x0f = (float)x0, x1f = (float)x1;
    const float y0f = (float)y0, y1f = (float)y1;
    const float wa = (x1f - x) * (y1f - y);   // (y0, x0)
    const float wb = (x1f - x) * (y - y0f);   // (y1, x0)
    const float wc = (x - x0f) * (y1f - y);   // (y0, x1)
    const float wd = (x - x0f) * (y - y0f);   // (y1, x1)

    const int q    = x0 & ~3;
    const int off0 = x0 - q;            // 0..3
    const int off1 = x1 - q;            // >3 => x1 outside quad
    const bool in_quad = (off1 <= 3);   // warp-uniform

    const int r0 = y0 * WW + q;
    const int r1 = y1 * WW + q;

    const float* __restrict__ base = feats + (size_t)b * CC * HWSZ;
    float* __restrict__ outp = out + ((size_t)(b * PTS_PER_BATCH + local)) * CC;

    if (in_quad) {
        #pragma unroll
        for (int k = 0; k < CC / 32; k++) {
            const int c = lane + 32 * k;
            const float* __restrict__ f = base + c * HWSZ;
            const float4 v0 = __ldg((const float4*)(f + r0));
            const float4 v1 = __ldg((const float4*)(f + r1));
            const float ia = f4_get(v0, off0);
            const float ic = f4_get(v0, off1);
            const float ib = f4_get(v1, off0);
            const float id = f4_get(v1, off1);
            outp[c] = wa * ia + wb * ib + wc * ic + wd * id;
        }
    } else {
        // off0 == 3, x1 in next quad: scalar taps for x1.
        const int o01 = y0 * WW + x1;
        const int o11 = y1 * WW + x1;
        #pragma unroll
        for (int k = 0; k < CC / 32; k++) {
            const int c = lane + 32 * k;
            const float* __restrict__ f = base + c * HWSZ;
            const float4 v0 = __ldg((const float4*)(f + r0));
            const float4 v1 = __ldg((const float4*)(f + r1));
            const float ic = __ldg(f + o01);
            const float id = __ldg(f + o11);
            outp[c] = wa * v0.w + wb * v1.w + wc * ic + wd * id;
        }
    }
}

extern "C" void kernel_launch(void* const* d_in, const int* in_sizes, int n_in,
                              void* d_out, int out_size)
{
    const float* feats = (const float*)d_in[0];
    const float* rois  = (const float*)d_in[1];
    float* out = (float*)d_out;

    const int blocks = BB * SEG;   // 4 * 896 = 3584
    bev_fused_kernel<<<blocks, THREADS>>>(feats, rois, out);
}

// round 6
// speedup vs baseline: 1.6710x; 1.6710x over previous
#include <cuda_runtime.h>

// BEVFeatureExtractorV2 — R6: channel-quartered schedule for DRAM row locality.
// feats: (B=4, C=256, H=256, W=256) fp32   rois: (B=4, N=512, 7) fp32
// out: (B, N, 5*C) fp32
//
// Traffic is compulsory (~250MB, verified R1-R5); rate (5.3/8 TB/s) is the
// binder. Each warp now handles one (b,n,p) point but only a 64-channel
// quarter; the quarter index is the SLOW grid dimension, so concurrent blocks
// confine the access stream to a 64MB region (4 near-sequential passes) ->
// better DRAM row-buffer hit rate. Geometry recomputed per pass (ALUs idle).

#define BB 4
#define NN 512
#define CC 256
#define HH 256
#define WW 256
#define NPTS 5
#define HWSZ (HH * WW)
#define NPOINTS (BB * NN * NPTS)    // 10240
#define QUARTERS 4
#define CQ (CC / QUARTERS)          // 64 channels per pass
#define WARPS_PER_BLOCK 2
#define PT_BLOCKS (NPOINTS / WARPS_PER_BLOCK)   // 5120 blocks per quarter

__device__ __forceinline__ float f4_get(const float4& v, int i) {
    return (i == 0) ? v.x : (i == 1) ? v.y : (i == 2) ? v.z : v.w;
}

__global__ __launch_bounds__(32 * WARPS_PER_BLOCK, 28) void bev_extract_kernel(
    const float* __restrict__ feats,
    const float* __restrict__ rois,
    float* __restrict__ out)
{
    const int quarter = blockIdx.x / PT_BLOCKS;          // slow dim: 4 passes
    const int pblk    = blockIdx.x % PT_BLOCKS;
    const int warp    = threadIdx.x >> 5;
    const int lane    = threadIdx.x & 31;
    const int point   = pblk * WARPS_PER_BLOCK + warp;   // 0..NPOINTS-1

    const int p = point % NPTS;
    const int n = (point / NPTS) % NN;
    const int b = point / (NPTS * NN);

    const float* roi = rois + (b * NN + n) * 7;
    const float cx = roi[0];
    const float cy = roi[1];
    const float dx = roi[3];
    const float dy = roi[4];
    const float ry = roi[6];

    float sn, cs;
    sincosf(ry, &sn, &cs);

    // rot(x, y) = (x*cos + y*sin, -x*sin + y*cos)  (row-vector * R)
    float px = cx, py = cy;
    const float hx = 0.5f * dx, hy = 0.5f * dy;
    if (p == 1)      { px = cx - hx * cs; py = cy + hx * sn; }
    else if (p == 2) { px = cx + hx * cs; py = cy - hx * sn; }
    else if (p == 3) { px = cx - hy * sn; py = cy - hy * cs; }
    else if (p == 4) { px = cx + hy * sn; py = cy + hy * cs; }

    const float x = (px + 51.2f) / 0.1f / 4.0f;
    const float y = (py + 51.2f) / 0.1f / 4.0f;

    const float xf = floorf(x);
    const float yf = floorf(y);
    int x0 = (int)xf,  x1 = (int)xf + 1;
    int y0 = (int)yf,  y1 = (int)yf + 1;
    x0 = min(max(x0, 0), WW - 1);
    x1 = min(max(x1, 0), WW - 1);
    y0 = min(max(y0, 0), HH - 1);
    y1 = min(max(y1, 0), HH - 1);

    const float x0f = (float)x0, x1f = (float)x1;
    const float y0f = (float)y0, y1f = (float)y1;
    const float wa = (x1f - x) * (y1f - y);   // (y0, x0)
    const float wb = (x1f - x) * (y - y0f);   // (y1, x0)
    const float wc = (x - x0f) * (y1f - y);   // (y0, x1)
    const float wd = (x - x0f) * (y - y0f);   // (y1, x1)

    const int q    = x0 & ~3;
    const int off0 = x0 - q;            // 0..3
    const int off1 = x1 - q;            // >3 => x1 outside quad
    const bool in_quad = (off1 <= 3);   // warp-uniform

    const int r0 = y0 * WW + q;
    const int r1 = y1 * WW + q;

    const float* __restrict__ base = feats + (size_t)b * CC * HWSZ;
    float* __restrict__ outp = out + (size_t)point * CC;

    const int c0 = quarter * CQ;

    if (in_quad) {
        #pragma unroll
        for (int k = 0; k < CQ / 32; k++) {
            const int c = c0 + lane + 32 * k;
            const float* __restrict__ f = base + c * HWSZ;
            const float4 v0 = __ldg((const float4*)(f + r0));
            const float4 v1 = __ldg((const float4*)(f + r1));
            const float ia = f4_get(v0, off0);
            const float ic = f4_get(v0, off1);
            const float ib = f4_get(v1, off0);
            const float id = f4_get(v1, off1);
            outp[c] = wa * ia + wb * ib + wc * ic + wd * id;
        }
    } else {
        // off0 == 3, x1 in next quad: scalar taps for x1.
        const int o01 = y0 * WW + x1;
        const int o11 = y1 * WW + x1;
        #pragma unroll
        for (int k = 0; k < CQ / 32; k++) {
            const int c = c0 + lane + 32 * k;
            const float* __restrict__ f = base + c * HWSZ;
            const float4 v0 = __ldg((const float4*)(f + r0));
            const float4 v1 = __ldg((const float4*)(f + r1));
            const float ic = __ldg(f + o01);
            const float id = __ldg(f + o11);
            outp[c] = wa * v0.w + wb * v1.w + wc * ic + wd * id;
        }
    }
}

extern "C" void kernel_launch(void* const* d_in, const int* in_sizes, int n_in,
                              void* d_out, int out_size)
{
    const float* feats = (const float*)d_in[0];
    const float* rois  = (const float*)d_in[1];
    float* out = (float*)d_out;

    const int blocks = QUARTERS * PT_BLOCKS;   // 4 * 5120 = 20480
    bev_extract_kernel<<<blocks, 32 * WARPS_PER_BLOCK>>>(feats, rois, out);
}

// round 7
// speedup vs baseline: 1.6997x; 1.0172x over previous
#include <cuda_runtime.h>

// BEVFeatureExtractorV2 — R7: 8 channel passes + streaming stores.
// feats: (B=4, C=256, H=256, W=256) fp32   rois: (B=4, N=512, 7) fp32
// out: (B, N, 5*C) fp32
//
// Established (R1-R6): traffic is compulsory (~210MB unique sectors + 10.5MB
// out); DRAM rate pinned ~5.5TB/s independent of request order. Channel-pass
// partitioning keeps the per-pass footprint L2-resident so every sector is
// fetched exactly once. R7: 8 passes (32MB footprint) to kill residual L2
// conflict misses, and evict-streaming output stores so writes don't push map
// lines out of L2.

#define BB 4
#define NN 512
#define CC 256
#define HH 256
#define WW 256
#define NPTS 5
#define HWSZ (HH * WW)
#define NPOINTS (BB * NN * NPTS)    // 10240
#define PASSES 8
#define CQ (CC / PASSES)            // 32 channels per pass
#define WARPS_PER_BLOCK 4
#define PT_BLOCKS (NPOINTS / WARPS_PER_BLOCK)   // 2560 blocks per pass

__device__ __forceinline__ float f4_get(const float4& v, int i) {
    return (i == 0) ? v.x : (i == 1) ? v.y : (i == 2) ? v.z : v.w;
}

__device__ __forceinline__ void stcs(float* p, float v) {
    asm volatile("st.global.cs.f32 [%0], %1;" :: "l"(p), "f"(v));
}

__global__ __launch_bounds__(32 * WARPS_PER_BLOCK, 14) void bev_extract_kernel(
    const float* __restrict__ feats,
    const float* __restrict__ rois,
    float* __restrict__ out)
{
    const int pass  = blockIdx.x / PT_BLOCKS;            // slow dim: 8 passes
    const int pblk  = blockIdx.x % PT_BLOCKS;
    const int warp  = threadIdx.x >> 5;
    const int lane  = threadIdx.x & 31;
    const int point = pblk * WARPS_PER_BLOCK + warp;     // 0..NPOINTS-1

    const int p = point % NPTS;
    const int n = (point / NPTS) % NN;
    const int b = point / (NPTS * NN);

    const float* roi = rois + (b * NN + n) * 7;
    const float cx = roi[0];
    const float cy = roi[1];
    const float dx = roi[3];
    const float dy = roi[4];
    const float ry = roi[6];

    float sn, cs;
    sincosf(ry, &sn, &cs);

    // rot(x, y) = (x*cos + y*sin, -x*sin + y*cos)  (row-vector * R)
    float px = cx, py = cy;
    const float hx = 0.5f * dx, hy = 0.5f * dy;
    if (p == 1)      { px = cx - hx * cs; py = cy + hx * sn; }
    else if (p == 2) { px = cx + hx * cs; py = cy - hx * sn; }
    else if (p == 3) { px = cx - hy * sn; py = cy - hy * cs; }
    else if (p == 4) { px = cx + hy * sn; py = cy + hy * cs; }

    const float x = (px + 51.2f) / 0.1f / 4.0f;
    const float y = (py + 51.2f) / 0.1f / 4.0f;

    const float xf = floorf(x);
    const float yf = floorf(y);
    int x0 = (int)xf,  x1 = (int)xf + 1;
    int y0 = (int)yf,  y1 = (int)yf + 1;
    x0 = min(max(x0, 0), WW - 1);
    x1 = min(max(x1, 0), WW - 1);
    y0 = min(max(y0, 0), HH - 1);
    y1 = min(max(y1, 0), HH - 1);

    const float x0f = (float)x0, x1f = (float)x1;
    const float y0f = (float)y0, y1f = (float)y1;
    const float wa = (x1f - x) * (y1f - y);   // (y0, x0)
    const float wb = (x1f - x) * (y - y0f);   // (y1, x0)
    const float wc = (x - x0f) * (y1f - y);   // (y0, x1)
    const float wd = (x - x0f) * (y - y0f);   // (y1, x1)

    const int q    = x0 & ~3;
    const int off0 = x0 - q;            // 0..3
    const int off1 = x1 - q;            // >3 => x1 outside quad
    const bool in_quad = (off1 <= 3);   // warp-uniform

    const int r0 = y0 * WW + q;
    const int r1 = y1 * WW + q;

    const float* __restrict__ base = feats + (size_t)b * CC * HWSZ;
    float* __restrict__ outp = out + (size_t)point * CC;

    const int c = pass * CQ + lane;     // CQ == 32: one channel per lane
    const float* __restrict__ f = base + c * HWSZ;

    if (in_quad) {
        const float4 v0 = __ldg((const float4*)(f + r0));
        const float4 v1 = __ldg((const float4*)(f + r1));
        const float ia = f4_get(v0, off0);
        const float ic = f4_get(v0, off1);
        const float ib = f4_get(v1, off0);
        const float id = f4_get(v1, off1);
        stcs(outp + c, wa * ia + wb * ib + wc * ic + wd * id);
    } else {
        // off0 == 3, x1 in next quad: scalar taps for x1.
        const int o01 = y0 * WW + x1;
        const int o11 = y1 * WW + x1;
        const float4 v0 = __ldg((const float4*)(f + r0));
        const float4 v1 = __ldg((const float4*)(f + r1));
        const float ic = __ldg(f + o01);
        const float id = __ldg(f + o11);
        stcs(outp + c, wa * v0.w + wb * v1.w + wc * ic + wd * id);
    }
}

extern "C" void kernel_launch(void* const* d_in, const int* in_sizes, int n_in,
                              void* d_out, int out_size)
{
    const float* feats = (const float*)d_in[0];
    const float* rois  = (const float*)d_in[1];
    float* out = (float*)d_out;

    const int blocks = PASSES * PT_BLOCKS;   // 8 * 2560 = 20480
    bev_extract_kernel<<<blocks, 32 * WARPS_PER_BLOCK>>>(feats, rois, out);
}